// round 4
// baseline (speedup 1.0000x reference)
#include <cuda_runtime.h>
#include <cstdint>
#include <math.h>

#define N_  4096
#define D_  64
#define T_  60
#define H_  128
#define G_  512
#define NT_ 245760
#define APAD 132   // padded row stride for h tile in smem

__device__ float g_xg[(size_t)T_*N_*G_];
__device__ float g_h[N_*H_];
__device__ float g_hb[N_*H_];
__device__ float g_WpT[D_*G_];
__device__ float g_biasP[G_];
__device__ float g_WhhT[H_*G_];
__device__ float g_bn1sum[D_], g_bn1sq[D_];
__device__ float g_bn2sum[H_], g_bn2sq[H_];
__device__ float g_wa1[H_], g_wa2[H_], g_cc[2];
__device__ float g_s1[N_], g_s2[N_];
__device__ float g_s1s[N_];
__device__ int   g_perm[N_];
__device__ float g_e1[N_], g_e2[N_];
__device__ double g_P1[(size_t)(N_+1)*H_];
__device__ double g_P2[(size_t)(N_+1)*H_];
__device__ double g_D1[N_+1], g_D2[N_+1];
__device__ float g_M;

__device__ __forceinline__ float sigmoidf_(float v) { return 1.f/(1.f + expf(-v)); }

__device__ __forceinline__ void cpa16(unsigned s, const void* g) {
    asm volatile("cp.async.ca.shared.global [%0], [%1], 16;" :: "r"(s), "l"(g));
}
__device__ __forceinline__ void cpa_commit() {
    asm volatile("cp.async.commit_group;");
}
template<int NPEND> __device__ __forceinline__ void cpa_wait() {
    asm volatile("cp.async.wait_group %0;" :: "n"(NPEND));
}

__global__ void k_init() {
    int idx = blockIdx.x*blockDim.x + threadIdx.x;
    if (idx < D_) { g_bn1sum[idx] = 0.f; g_bn1sq[idx] = 0.f; }
    if (idx < H_) { g_bn2sum[idx] = 0.f; g_bn2sq[idx] = 0.f; }
}

__global__ void k_bn1(const float* __restrict__ x) {
    int d  = blockIdx.x;
    int n0 = blockIdx.y * 256;
    float s = 0.f, q = 0.f;
    for (int idx = threadIdx.x; idx < 256*T_; idx += 256) {
        int n = n0 + idx / T_;
        int t = idx - (idx / T_) * T_;
        float v = x[(size_t)n*(D_*T_) + d*T_ + t];
        s += v; q += v*v;
    }
    __shared__ float ss[256], qq[256];
    ss[threadIdx.x] = s; qq[threadIdx.x] = q;
    __syncthreads();
    for (int st = 128; st > 0; st >>= 1) {
        if (threadIdx.x < st) { ss[threadIdx.x] += ss[threadIdx.x+st]; qq[threadIdx.x] += qq[threadIdx.x+st]; }
        __syncthreads();
    }
    if (threadIdx.x == 0) { atomicAdd(&g_bn1sum[d], ss[0]); atomicAdd(&g_bn1sq[d], qq[0]); }
}

__global__ void k_prep(const float* __restrict__ bn1g, const float* __restrict__ bn1b,
                       const float* __restrict__ W_ih, const float* __restrict__ W_hh,
                       const float* __restrict__ b_ih, const float* __restrict__ b_hh,
                       const float* __restrict__ W_t,  const float* __restrict__ b_t,
                       const float* __restrict__ a) {
    __shared__ float sc[D_], sf[D_];
    int g = threadIdx.x;  // 512 threads
    if (g < D_) {
        float inv = 1.f / (float)NT_;
        float m   = g_bn1sum[g] * inv;
        float var = g_bn1sq[g]  * inv - m*m;
        float rs  = rsqrtf(var + 1e-5f);
        sc[g] = rs * bn1g[g];
        sf[g] = bn1b[g] - m * rs * bn1g[g];
    }
    __syncthreads();
    float b = b_ih[g] + b_hh[g];
    for (int d = 0; d < D_; ++d) {
        float w = W_ih[g*D_ + d];
        b += w * sf[d];
        g_WpT[d*G_ + g] = w * sc[d];
    }
    g_biasP[g] = b;
    for (int k = 0; k < H_; ++k) g_WhhT[k*G_ + g] = W_hh[g*H_ + k];
    if (g < H_) {
        float w1 = 0.f, w2 = 0.f;
        for (int h = 0; h < H_; ++h) { float wt = W_t[h*H_ + g]; w1 += wt*a[h]; w2 += wt*a[H_+h]; }
        g_wa1[g] = w1; g_wa2[g] = w2;
    }
    if (g == 0) {
        float c1 = 0.f, c2 = 0.f;
        for (int h = 0; h < H_; ++h) { c1 += b_t[h]*a[h]; c2 += b_t[h]*a[H_+h]; }
        g_cc[0] = c1; g_cc[1] = c2;
    }
}

// xg GEMM: [245760 x 64] @ [64 x 512], BN1 fused via W'
__global__ void k_xg(const float* __restrict__ x) {
    __shared__ float a_sh[64][64];    // [k][m]
    __shared__ float b_sh[64][128];   // [k][g]
    int tid = threadIdx.x;
    int r0  = blockIdx.x * 64;
    int g0  = blockIdx.y * 128;
    {
        int m  = tid & 63;
        int kh = tid >> 6;
        int r  = r0 + m;
        int n  = r / T_;
        int tt = r - n*T_;
        const float* xp = x + (size_t)n*(D_*T_) + tt;
        #pragma unroll
        for (int i = 0; i < 32; ++i) {
            int k = 2*i + kh;
            a_sh[k][m] = xp[(size_t)k*T_];
        }
    }
    #pragma unroll
    for (int i = 0; i < 16; ++i) {
        int idx4 = i*128 + tid;
        int kk = idx4 >> 5, gq = idx4 & 31;
        *(float4*)&b_sh[kk][gq*4] = *(const float4*)&g_WpT[(size_t)kk*G_ + g0 + gq*4];
    }
    __syncthreads();
    int cc = tid & 15, rr = tid >> 4;
    float acc[8][8];
    #pragma unroll
    for (int i = 0; i < 8; ++i)
        #pragma unroll
        for (int j = 0; j < 8; ++j) acc[i][j] = 0.f;
    #pragma unroll 8
    for (int k = 0; k < 64; ++k) {
        float4 b0 = *(float4*)&b_sh[k][cc*8];
        float4 b1 = *(float4*)&b_sh[k][cc*8 + 4];
        #pragma unroll
        for (int i = 0; i < 8; ++i) {
            float av = a_sh[k][rr*8 + i];
            acc[i][0] += av*b0.x; acc[i][1] += av*b0.y; acc[i][2] += av*b0.z; acc[i][3] += av*b0.w;
            acc[i][4] += av*b1.x; acc[i][5] += av*b1.y; acc[i][6] += av*b1.z; acc[i][7] += av*b1.w;
        }
    }
    float4 bb0 = *(const float4*)&g_biasP[g0 + cc*8];
    float4 bb1 = *(const float4*)&g_biasP[g0 + cc*8 + 4];
    #pragma unroll
    for (int i = 0; i < 8; ++i) {
        int r  = r0 + rr*8 + i;
        int n  = r / T_;
        int tt = r - n*T_;
        float* dst = g_xg + ((size_t)tt*N_ + n)*G_ + g0 + cc*8;
        float4 o0 = make_float4(acc[i][0]+bb0.x, acc[i][1]+bb0.y, acc[i][2]+bb0.z, acc[i][3]+bb0.w);
        float4 o1 = make_float4(acc[i][4]+bb1.x, acc[i][5]+bb1.y, acc[i][6]+bb1.z, acc[i][7]+bb1.w);
        *(float4*)&dst[0] = o0;
        *(float4*)&dst[4] = o1;
    }
}

// ---------------- fused persistent LSTM ------------------------------------
// grid=128 blocks (32 rows each), block=256 threads.
// Thread (rr=tid>>6, cc=tid&63) owns rows rr*8..+8 and channels {2cc,2cc+1}
// across all four gate groups -> cell update fully in-register.
__global__ void __launch_bounds__(256, 1) k_lstm() {
    extern __shared__ float sm[];
    float* bs = sm;                     // [2][32][512] W_hh chunks (double buffer)
    float* as = sm + 2*32*512;          // [32][APAD]   h tile
    const int tid = threadIdx.x;
    const int n0  = blockIdx.x * 32;
    const int cc  = tid & 63;
    const int rr  = tid >> 6;

    for (int i = tid; i < 32*APAD; i += 256) as[i] = 0.f;
    float creg[8][2];
    #pragma unroll
    for (int i = 0; i < 8; ++i) { creg[i][0] = 0.f; creg[i][1] = 0.f; }

    unsigned bs_u = (unsigned)__cvta_generic_to_shared(bs);
    __syncthreads();

    {   // prefetch chunk 0 into buffer 0
        const float* src = g_WhhT;
        #pragma unroll
        for (int it = 0; it < 16; ++it) {
            int f = it*256 + tid;
            cpa16(bs_u + (unsigned)f*16u, src + (size_t)f*4);
        }
        cpa_commit();
    }

    for (int t = 0; t < T_; ++t) {
        float acc[8][8];
        #pragma unroll
        for (int i = 0; i < 8; ++i)
            #pragma unroll
            for (int j = 0; j < 8; ++j) acc[i][j] = 0.f;

        #pragma unroll
        for (int kc = 0; kc < 4; ++kc) {
            if (kc < 3) {
                const float* src = g_WhhT + (size_t)(kc+1)*32*G_;
                unsigned dst = bs_u + (unsigned)(((kc+1)&1)*32*512)*4u;
                #pragma unroll
                for (int it = 0; it < 16; ++it) {
                    int f = it*256 + tid;
                    cpa16(dst + (unsigned)f*16u, src + (size_t)f*4);
                }
                cpa_commit();
                cpa_wait<1>();
            } else {
                cpa_wait<0>();
            }
            __syncthreads();
            const float* B = bs + (kc&1)*32*512;
            const float* A = as + (rr*8)*APAD + kc*32;
            #pragma unroll
            for (int kk = 0; kk < 32; ++kk) {
                float2 b0 = *(const float2*)&B[kk*512 +   0 + 2*cc];
                float2 b1 = *(const float2*)&B[kk*512 + 128 + 2*cc];
                float2 b2 = *(const float2*)&B[kk*512 + 256 + 2*cc];
                float2 b3 = *(const float2*)&B[kk*512 + 384 + 2*cc];
                #pragma unroll
                for (int i = 0; i < 8; ++i) {
                    float av = A[i*APAD + kk];
                    acc[i][0] += av*b0.x; acc[i][1] += av*b0.y;
                    acc[i][2] += av*b1.x; acc[i][3] += av*b1.y;
                    acc[i][4] += av*b2.x; acc[i][5] += av*b2.y;
                    acc[i][6] += av*b3.x; acc[i][7] += av*b3.y;
                }
            }
            __syncthreads();
        }

        if (t < T_-1) {   // prefetch chunk 0 for next step during epilogue
            const float* src = g_WhhT;
            #pragma unroll
            for (int it = 0; it < 16; ++it) {
                int f = it*256 + tid;
                cpa16(bs_u + (unsigned)f*16u, src + (size_t)f*4);
            }
            cpa_commit();
        }

        const float* xgb = g_xg + ((size_t)t*N_ + n0)*G_;
        #pragma unroll
        for (int i = 0; i < 8; ++i) {
            int r = rr*8 + i;
            const float* xp = xgb + (size_t)r*G_ + 2*cc;
            float2 xi = *(const float2*)&xp[0];
            float2 xf = *(const float2*)&xp[128];
            float2 xg = *(const float2*)&xp[256];
            float2 xo = *(const float2*)&xp[384];
            float h0, h1;
            {
                float iv = sigmoidf_(acc[i][0] + xi.x);
                float fv = sigmoidf_(acc[i][2] + xf.x);
                float gv = tanhf    (acc[i][4] + xg.x);
                float ov = sigmoidf_(acc[i][6] + xo.x);
                float cn = fv * creg[i][0] + iv * gv;
                creg[i][0] = cn;
                h0 = ov * tanhf(cn);
            }
            {
                float iv = sigmoidf_(acc[i][1] + xi.y);
                float fv = sigmoidf_(acc[i][3] + xf.y);
                float gv = tanhf    (acc[i][5] + xg.y);
                float ov = sigmoidf_(acc[i][7] + xo.y);
                float cn = fv * creg[i][1] + iv * gv;
                creg[i][1] = cn;
                h1 = ov * tanhf(cn);
            }
            *(float2*)&as[r*APAD + 2*cc] = make_float2(h0, h1);
        }
        __syncthreads();
    }

    for (int i = tid; i < 32*H_; i += 256) {
        int r = i >> 7, ch = i & 127;
        g_h[(size_t)(n0 + r)*H_ + ch] = as[r*APAD + ch];
    }
}

__global__ void k_bn2s() {
    int ch = threadIdx.x;
    int n0 = blockIdx.x * 32;
    float s = 0.f, q = 0.f;
    for (int r = 0; r < 32; ++r) { float v = g_h[(size_t)(n0+r)*H_ + ch]; s += v; q += v*v; }
    atomicAdd(&g_bn2sum[ch], s);
    atomicAdd(&g_bn2sq[ch],  q);
}

__global__ void k_bn2a(const float* __restrict__ g2, const float* __restrict__ b2) {
    int n = blockIdx.x, ch = threadIdx.x;
    float inv = 1.f / (float)N_;
    float m   = g_bn2sum[ch] * inv;
    float var = g_bn2sq[ch]  * inv - m*m;
    float hb  = (g_h[(size_t)n*H_ + ch] - m) * rsqrtf(var + 1e-5f) * g2[ch] + b2[ch];
    g_hb[(size_t)n*H_ + ch] = hb;
    __shared__ float r1[H_], r2[H_];
    r1[ch] = hb * g_wa1[ch];
    r2[ch] = hb * g_wa2[ch];
    __syncthreads();
    for (int s = 64; s > 0; s >>= 1) {
        if (ch < s) { r1[ch] += r1[ch+s]; r2[ch] += r2[ch+s]; }
        __syncthreads();
    }
    if (ch == 0) { g_s1[n] = r1[0] + g_cc[0]; g_s2[n] = r2[0] + g_cc[1]; }
}

__global__ void k_sort() {
    __shared__ float v[N_];
    __shared__ int   p[N_];
    int tid = threadIdx.x;
    for (int i = tid; i < N_; i += 1024) { v[i] = g_s1[i]; p[i] = i; }
    __syncthreads();
    for (int kk = 2; kk <= N_; kk <<= 1) {
        for (int j = kk >> 1; j > 0; j >>= 1) {
            for (int i = tid; i < N_; i += 1024) {
                int ixj = i ^ j;
                if (ixj > i) {
                    bool up = ((i & kk) == 0);
                    bool sw = up ? (v[i] < v[ixj]) : (v[i] > v[ixj]);
                    if (sw) {
                        float tv = v[i]; v[i] = v[ixj]; v[ixj] = tv;
                        int   tp = p[i]; p[i] = p[ixj]; p[ixj] = tp;
                    }
                }
            }
            __syncthreads();
        }
    }
    for (int i = tid; i < N_; i += 1024) { g_s1s[i] = v[i]; g_perm[i] = p[i]; }
}

__global__ void k_exp() {
    int i = blockIdx.x*blockDim.x + threadIdx.x;
    float M = g_s1s[0];
    if (i == 0) g_M = M;
    if (i < N_) {
        g_e1[i] = expf(g_s1s[i] - M);
        g_e2[i] = expf(0.01f * g_s1s[i]);
    }
}

__global__ void k_prefix_ch() {
    int ch  = blockIdx.x;
    int tid = threadIdx.x;   // 256
    __shared__ double tsum[256];
    int base = tid * 16;
    {
        double loc[16]; double s = 0.0;
        #pragma unroll
        for (int i = 0; i < 16; ++i) {
            int j = base + i;
            s += (double)g_e1[j] * (double)g_hb[(size_t)g_perm[j]*H_ + ch];
            loc[i] = s;
        }
        tsum[tid] = s; __syncthreads();
        for (int off = 1; off < 256; off <<= 1) {
            double vv = (tid >= off) ? tsum[tid-off] : 0.0;
            __syncthreads();
            tsum[tid] += vv;
            __syncthreads();
        }
        double excl = tsum[tid] - s;
        if (tid == 0) g_P1[ch] = 0.0;
        #pragma unroll
        for (int i = 0; i < 16; ++i) g_P1[(size_t)(base+i+1)*H_ + ch] = excl + loc[i];
    }
    __syncthreads();
    {
        double loc[16]; double s = 0.0;
        #pragma unroll
        for (int i = 0; i < 16; ++i) {
            int j = base + i;
            s += (double)g_e2[j] * (double)g_hb[(size_t)g_perm[j]*H_ + ch];
            loc[i] = s;
        }
        tsum[tid] = s; __syncthreads();
        for (int off = 1; off < 256; off <<= 1) {
            double vv = (tid >= off) ? tsum[tid-off] : 0.0;
            __syncthreads();
            tsum[tid] += vv;
            __syncthreads();
        }
        double excl = tsum[tid] - s;
        if (tid == 0) g_P2[ch] = 0.0;
        #pragma unroll
        for (int i = 0; i < 16; ++i) g_P2[(size_t)(base+i+1)*H_ + ch] = excl + loc[i];
    }
}

__global__ void k_prefix_scalar() {
    int tid = threadIdx.x;   // 256
    __shared__ double tsum[256];
    int base = tid * 16;
    for (int pass = 0; pass < 2; ++pass) {
        const float* e = pass ? g_e2 : g_e1;
        double* P = pass ? g_D2 : g_D1;
        double loc[16]; double s = 0.0;
        #pragma unroll
        for (int i = 0; i < 16; ++i) { s += (double)e[base+i]; loc[i] = s; }
        tsum[tid] = s; __syncthreads();
        for (int off = 1; off < 256; off <<= 1) {
            double vv = (tid >= off) ? tsum[tid-off] : 0.0;
            __syncthreads();
            tsum[tid] += vv;
            __syncthreads();
        }
        double excl = tsum[tid] - s;
        if (tid == 0) P[0] = 0.0;
        #pragma unroll
        for (int i = 0; i < 16; ++i) P[base+i+1] = excl + loc[i];
        __syncthreads();
    }
}

__global__ void k_att(float* __restrict__ out,
                      const float* __restrict__ Wfc, const float* __restrict__ bfc,
                      const float* __restrict__ Wout, const float* __restrict__ bout) {
    int i   = blockIdx.x;
    int tid = threadIdx.x;   // 128
    __shared__ float h2s[H_];
    __shared__ float red[H_];
    __shared__ int   ksh;
    float s2i = g_s2[i];
    if (tid == 0) {
        float thr = -s2i;
        int lo = 0, hi = N_;
        while (lo < hi) { int mid = (lo+hi) >> 1; if (g_s1s[mid] >= thr) lo = mid+1; else hi = mid; }
        ksh = lo;
    }
    __syncthreads();
    int k = ksh;
    double f1 = exp((double)s2i + (double)g_M);
    double f2 = exp(0.01 * (double)s2i);
    double den = f1 * g_D1[k] + f2 * (g_D2[N_] - g_D2[k]);
    double num = f1 * g_P1[(size_t)k*H_ + tid]
               + f2 * (g_P2[(size_t)N_*H_ + tid] - g_P2[(size_t)k*H_ + tid]);
    h2s[tid] = (float)(num / den) + g_hb[(size_t)i*H_ + tid];
    __syncthreads();
    float acc = bfc[tid];
    #pragma unroll 8
    for (int ch = 0; ch < H_; ++ch) acc += Wfc[tid*H_ + ch] * h2s[ch];
    float h3 = acc >= 0.f ? acc : 0.01f * acc;
    red[tid] = h3 * Wout[tid];
    __syncthreads();
    for (int s = 64; s > 0; s >>= 1) {
        if (tid < s) red[tid] += red[tid + s];
        __syncthreads();
    }
    if (tid == 0) out[i] = sigmoidf_(red[0] + bout[0]);
}

extern "C" void kernel_launch(void* const* d_in, const int* in_sizes, int n_in,
                              void* d_out, int out_size) {
    const float* x     = (const float*)d_in[0];
    const float* bn1g  = (const float*)d_in[1];
    const float* bn1b  = (const float*)d_in[2];
    const float* W_ih  = (const float*)d_in[3];
    const float* W_hh  = (const float*)d_in[4];
    const float* b_ih  = (const float*)d_in[5];
    const float* b_hh  = (const float*)d_in[6];
    const float* bn2g  = (const float*)d_in[7];
    const float* bn2b  = (const float*)d_in[8];
    const float* W_t   = (const float*)d_in[9];
    const float* b_t   = (const float*)d_in[10];
    const float* a     = (const float*)d_in[11];
    const float* W_fc  = (const float*)d_in[12];
    const float* b_fc  = (const float*)d_in[13];
    const float* W_out = (const float*)d_in[14];
    const float* b_out = (const float*)d_in[15];
    float* out = (float*)d_out;

    const int lstm_smem = (2*32*512 + 32*APAD) * (int)sizeof(float);  // ~148 KB
    cudaFuncSetAttribute(k_lstm, cudaFuncAttributeMaxDynamicSharedMemorySize, lstm_smem);

    k_init<<<1, 256>>>();
    k_bn1<<<dim3(D_, 16), 256>>>(x);
    k_prep<<<1, 512>>>(bn1g, bn1b, W_ih, W_hh, b_ih, b_hh, W_t, b_t, a);
    k_xg<<<dim3(NT_/64, 4), 128>>>(x);
    k_lstm<<<128, 256, lstm_smem>>>();
    k_bn2s<<<N_/32, 128>>>();
    k_bn2a<<<N_, 128>>>(bn2g, bn2b);
    k_sort<<<1, 1024>>>();
    k_exp<<<(N_+255)/256, 256>>>();
    k_prefix_ch<<<H_, 256>>>();
    k_prefix_scalar<<<1, 256>>>();
    k_att<<<N_, 128>>>(out, W_fc, b_fc, W_out, b_out);
}

// round 7
// speedup vs baseline: 1.3629x; 1.3629x over previous
#include <cuda_runtime.h>
#include <cstdint>
#include <math.h>

#define N_  4096
#define D_  64
#define T_  60
#define H_  128
#define G_  512
#define NT_ 245760

// gate dimension stored INTERLEAVED: jcol = ch*4 + gate (0=i,1=f,2=g,3=o).
// h is ping-pong buffered across timesteps to avoid read/write races in k_gc.

__device__ float g_xg[(size_t)T_*N_*G_];
__device__ float g_hbuf[2][N_*H_];
__device__ float g_c[N_*H_];
__device__ float g_hb[N_*H_];
__device__ float g_WpT[D_*G_];
__device__ float g_biasP[G_];
__device__ float g_Whh_i[H_*G_];
__device__ float g_bn1sum[D_], g_bn1sq[D_];
__device__ float g_bn2sum[H_], g_bn2sq[H_];
__device__ float g_wa1[H_], g_wa2[H_], g_cc[2];
__device__ float g_s1[N_], g_s2[N_];
__device__ float g_s1s[N_];
__device__ int   g_perm[N_];
__device__ float g_e1[N_], g_e2[N_];
__device__ double g_P1[(size_t)(N_+1)*H_];
__device__ double g_P2[(size_t)(N_+1)*H_];
__device__ double g_D1[N_+1], g_D2[N_+1];
__device__ float g_M;

__device__ __forceinline__ float sigmoidf_(float v) { return 1.f/(1.f + expf(-v)); }

__global__ void k_init() {
    int idx = blockIdx.x*blockDim.x + threadIdx.x;
    if (idx < N_*H_) { g_hbuf[0][idx] = 0.f; g_c[idx] = 0.f; }
    if (idx < D_)    { g_bn1sum[idx] = 0.f; g_bn1sq[idx] = 0.f; }
    if (idx < H_)    { g_bn2sum[idx] = 0.f; g_bn2sq[idx] = 0.f; }
}

__global__ void k_bn1(const float* __restrict__ x) {
    int d  = blockIdx.x;
    int n0 = blockIdx.y * 256;
    float s = 0.f, q = 0.f;
    for (int idx = threadIdx.x; idx < 256*T_; idx += 256) {
        int n = n0 + idx / T_;
        int t = idx - (idx / T_) * T_;
        float v = x[(size_t)n*(D_*T_) + d*T_ + t];
        s += v; q += v*v;
    }
    __shared__ float ss[256], qq[256];
    ss[threadIdx.x] = s; qq[threadIdx.x] = q;
    __syncthreads();
    for (int st = 128; st > 0; st >>= 1) {
        if (threadIdx.x < st) { ss[threadIdx.x] += ss[threadIdx.x+st]; qq[threadIdx.x] += qq[threadIdx.x+st]; }
        __syncthreads();
    }
    if (threadIdx.x == 0) { atomicAdd(&g_bn1sum[d], ss[0]); atomicAdd(&g_bn1sq[d], qq[0]); }
}

__global__ void k_prep(const float* __restrict__ bn1g, const float* __restrict__ bn1b,
                       const float* __restrict__ W_ih, const float* __restrict__ W_hh,
                       const float* __restrict__ b_ih, const float* __restrict__ b_hh,
                       const float* __restrict__ W_t,  const float* __restrict__ b_t,
                       const float* __restrict__ a) {
    __shared__ float sc[D_], sf[D_];
    int g = threadIdx.x;  // 512 threads; g = gate*128 + ch (original layout)
    if (g < D_) {
        float inv = 1.f / (float)NT_;
        float m   = g_bn1sum[g] * inv;
        float var = g_bn1sq[g]  * inv - m*m;
        float rs  = rsqrtf(var + 1e-5f);
        sc[g] = rs * bn1g[g];
        sf[g] = bn1b[g] - m * rs * bn1g[g];
    }
    __syncthreads();
    int jcol = (g & 127) * 4 + (g >> 7);   // interleaved column
    float b = b_ih[g] + b_hh[g];
    for (int d = 0; d < D_; ++d) {
        float w = W_ih[g*D_ + d];
        b += w * sf[d];
        g_WpT[d*G_ + jcol] = w * sc[d];
    }
    g_biasP[jcol] = b;
    for (int k = 0; k < H_; ++k) g_Whh_i[k*G_ + jcol] = W_hh[g*H_ + k];
    if (g < H_) {
        float w1 = 0.f, w2 = 0.f;
        for (int h = 0; h < H_; ++h) { float wt = W_t[h*H_ + g]; w1 += wt*a[h]; w2 += wt*a[H_+h]; }
        g_wa1[g] = w1; g_wa2[g] = w2;
    }
    if (g == 0) {
        float c1 = 0.f, c2 = 0.f;
        for (int h = 0; h < H_; ++h) { c1 += b_t[h]*a[h]; c2 += b_t[h]*a[H_+h]; }
        g_cc[0] = c1; g_cc[1] = c2;
    }
}

// xg GEMM: [245760 x 64] @ [64 x 512], BN1 fused; output interleaved cols
__global__ void k_xg(const float* __restrict__ x) {
    __shared__ float a_sh[64][64];    // [k][m]
    __shared__ float b_sh[64][128];   // [k][jcol]
    int tid = threadIdx.x;
    int r0  = blockIdx.x * 64;
    int g0  = blockIdx.y * 128;
    {
        int m  = tid & 63;
        int kh = tid >> 6;
        int r  = r0 + m;
        int n  = r / T_;
        int tt = r - n*T_;
        const float* xp = x + (size_t)n*(D_*T_) + tt;
        #pragma unroll
        for (int i = 0; i < 32; ++i) {
            int k = 2*i + kh;
            a_sh[k][m] = xp[(size_t)k*T_];
        }
    }
    #pragma unroll
    for (int i = 0; i < 16; ++i) {
        int idx4 = i*128 + tid;
        int kk = idx4 >> 5, gq = idx4 & 31;
        *(float4*)&b_sh[kk][gq*4] = *(const float4*)&g_WpT[(size_t)kk*G_ + g0 + gq*4];
    }
    __syncthreads();
    int cc = tid & 15, rr = tid >> 4;
    float acc[8][8];
    #pragma unroll
    for (int i = 0; i < 8; ++i)
        #pragma unroll
        for (int j = 0; j < 8; ++j) acc[i][j] = 0.f;
    #pragma unroll 8
    for (int k = 0; k < 64; ++k) {
        float4 b0 = *(float4*)&b_sh[k][cc*8];
        float4 b1 = *(float4*)&b_sh[k][cc*8 + 4];
        #pragma unroll
        for (int i = 0; i < 8; ++i) {
            float av = a_sh[k][rr*8 + i];
            acc[i][0] += av*b0.x; acc[i][1] += av*b0.y; acc[i][2] += av*b0.z; acc[i][3] += av*b0.w;
            acc[i][4] += av*b1.x; acc[i][5] += av*b1.y; acc[i][6] += av*b1.z; acc[i][7] += av*b1.w;
        }
    }
    float4 bb0 = *(const float4*)&g_biasP[g0 + cc*8];
    float4 bb1 = *(const float4*)&g_biasP[g0 + cc*8 + 4];
    #pragma unroll
    for (int i = 0; i < 8; ++i) {
        int r  = r0 + rr*8 + i;
        int n  = r / T_;
        int tt = r - n*T_;
        float* dst = g_xg + ((size_t)tt*N_ + n)*G_ + g0 + cc*8;
        float4 o0 = make_float4(acc[i][0]+bb0.x, acc[i][1]+bb0.y, acc[i][2]+bb0.z, acc[i][3]+bb0.w);
        float4 o1 = make_float4(acc[i][4]+bb1.x, acc[i][5]+bb1.y, acc[i][6]+bb1.z, acc[i][7]+bb1.w);
        *(float4*)&dst[0] = o0;
        *(float4*)&dst[4] = o1;
    }
}

// fused gates GEMM + LSTM cell. Reads h from g_hbuf[t&1], writes g_hbuf[(t+1)&1].
__global__ void k_gc(int tstep) {
    __shared__ float a_sh[64][64];    // [m][k]
    __shared__ float b_sh[64][128];   // [k][jcol]
    const float* hin  = g_hbuf[tstep & 1];
    float*       hout = g_hbuf[(tstep + 1) & 1];
    int tid = threadIdx.x;
    int n0  = blockIdx.x * 64;
    int j0  = blockIdx.y * 128;
    int cc  = tid & 15, rr = tid >> 4;
    float acc[8][8];
    #pragma unroll
    for (int i = 0; i < 8; ++i)
        #pragma unroll
        for (int j = 0; j < 8; ++j) acc[i][j] = 0.f;
    for (int kc = 0; kc < 2; ++kc) {
        #pragma unroll
        for (int i = 0; i < 8; ++i) {
            int idx4 = i*128 + tid;
            int row = idx4 >> 4, q = idx4 & 15;
            *(float4*)&a_sh[row][q*4] =
                *(const float4*)&hin[(size_t)(n0+row)*H_ + kc*64 + q*4];
        }
        #pragma unroll
        for (int i = 0; i < 16; ++i) {
            int idx4 = i*128 + tid;
            int kk = idx4 >> 5, gq = idx4 & 31;
            *(float4*)&b_sh[kk][gq*4] =
                *(const float4*)&g_Whh_i[(size_t)(kc*64+kk)*G_ + j0 + gq*4];
        }
        __syncthreads();
        #pragma unroll 8
        for (int k = 0; k < 64; ++k) {
            float4 b0 = *(float4*)&b_sh[k][cc*8];
            float4 b1 = *(float4*)&b_sh[k][cc*8 + 4];
            #pragma unroll
            for (int i = 0; i < 8; ++i) {
                float av = a_sh[rr*8 + i][k];
                acc[i][0] += av*b0.x; acc[i][1] += av*b0.y; acc[i][2] += av*b0.z; acc[i][3] += av*b0.w;
                acc[i][4] += av*b1.x; acc[i][5] += av*b1.y; acc[i][6] += av*b1.z; acc[i][7] += av*b1.w;
            }
        }
        __syncthreads();
    }
    const float* xgb = g_xg + (size_t)tstep*N_*G_;   // FIXED: no n0 here (off uses global n)
    int chA = (j0 >> 2) + 2*cc;
    #pragma unroll
    for (int i = 0; i < 8; ++i) {
        int n = n0 + rr*8 + i;
        size_t off = (size_t)n*G_ + j0 + cc*8;
        float4 x0 = *(const float4*)&xgb[off];
        float4 x1 = *(const float4*)&xgb[off + 4];
        size_t cidx = (size_t)n*H_ + chA;
        float2 cp = *(const float2*)&g_c[cidx];
        float h0, h1, c0, c1;
        {
            float iv = sigmoidf_(acc[i][0] + x0.x);
            float fv = sigmoidf_(acc[i][1] + x0.y);
            float gv = tanhf    (acc[i][2] + x0.z);
            float ov = sigmoidf_(acc[i][3] + x0.w);
            c0 = fv * cp.x + iv * gv;
            h0 = ov * tanhf(c0);
        }
        {
            float iv = sigmoidf_(acc[i][4] + x1.x);
            float fv = sigmoidf_(acc[i][5] + x1.y);
            float gv = tanhf    (acc[i][6] + x1.z);
            float ov = sigmoidf_(acc[i][7] + x1.w);
            c1 = fv * cp.y + iv * gv;
            h1 = ov * tanhf(c1);
        }
        *(float2*)&g_c[cidx]  = make_float2(c0, c1);
        *(float2*)&hout[cidx] = make_float2(h0, h1);
    }
}

__global__ void k_bn2s() {
    int ch = threadIdx.x;
    int n0 = blockIdx.x * 32;
    const float* hfin = g_hbuf[T_ & 1];
    float s = 0.f, q = 0.f;
    for (int r = 0; r < 32; ++r) { float v = hfin[(size_t)(n0+r)*H_ + ch]; s += v; q += v*v; }
    atomicAdd(&g_bn2sum[ch], s);
    atomicAdd(&g_bn2sq[ch],  q);
}

__global__ void k_bn2a(const float* __restrict__ g2, const float* __restrict__ b2) {
    int n = blockIdx.x, ch = threadIdx.x;
    const float* hfin = g_hbuf[T_ & 1];
    float inv = 1.f / (float)N_;
    float m   = g_bn2sum[ch] * inv;
    float var = g_bn2sq[ch]  * inv - m*m;
    float hb  = (hfin[(size_t)n*H_ + ch] - m) * rsqrtf(var + 1e-5f) * g2[ch] + b2[ch];
    g_hb[(size_t)n*H_ + ch] = hb;
    __shared__ float r1[H_], r2[H_];
    r1[ch] = hb * g_wa1[ch];
    r2[ch] = hb * g_wa2[ch];
    __syncthreads();
    for (int s = 64; s > 0; s >>= 1) {
        if (ch < s) { r1[ch] += r1[ch+s]; r2[ch] += r2[ch+s]; }
        __syncthreads();
    }
    if (ch == 0) { g_s1[n] = r1[0] + g_cc[0]; g_s2[n] = r2[0] + g_cc[1]; }
}

__global__ void k_sort() {
    __shared__ float v[N_];
    __shared__ int   p[N_];
    int tid = threadIdx.x;
    for (int i = tid; i < N_; i += 1024) { v[i] = g_s1[i]; p[i] = i; }
    __syncthreads();
    for (int kk = 2; kk <= N_; kk <<= 1) {
        for (int j = kk >> 1; j > 0; j >>= 1) {
            for (int i = tid; i < N_; i += 1024) {
                int ixj = i ^ j;
                if (ixj > i) {
                    bool up = ((i & kk) == 0);
                    bool sw = up ? (v[i] < v[ixj]) : (v[i] > v[ixj]);
                    if (sw) {
                        float tv = v[i]; v[i] = v[ixj]; v[ixj] = tv;
                        int   tp = p[i]; p[i] = p[ixj]; p[ixj] = tp;
                    }
                }
            }
            __syncthreads();
        }
    }
    for (int i = tid; i < N_; i += 1024) { g_s1s[i] = v[i]; g_perm[i] = p[i]; }
}

__global__ void k_exp() {
    int i = blockIdx.x*blockDim.x + threadIdx.x;
    float M = g_s1s[0];
    if (i == 0) g_M = M;
    if (i < N_) {
        g_e1[i] = expf(g_s1s[i] - M);
        g_e2[i] = expf(0.01f * g_s1s[i]);
    }
}

__global__ void k_prefix_ch() {
    int ch  = blockIdx.x;
    int tid = threadIdx.x;   // 256
    __shared__ double tsum[256];
    int base = tid * 16;
    {
        double loc[16]; double s = 0.0;
        #pragma unroll
        for (int i = 0; i < 16; ++i) {
            int j = base + i;
            s += (double)g_e1[j] * (double)g_hb[(size_t)g_perm[j]*H_ + ch];
            loc[i] = s;
        }
        tsum[tid] = s; __syncthreads();
        for (int off = 1; off < 256; off <<= 1) {
            double vv = (tid >= off) ? tsum[tid-off] : 0.0;
            __syncthreads();
            tsum[tid] += vv;
            __syncthreads();
        }
        double excl = tsum[tid] - s;
        if (tid == 0) g_P1[ch] = 0.0;
        #pragma unroll
        for (int i = 0; i < 16; ++i) g_P1[(size_t)(base+i+1)*H_ + ch] = excl + loc[i];
    }
    __syncthreads();
    {
        double loc[16]; double s = 0.0;
        #pragma unroll
        for (int i = 0; i < 16; ++i) {
            int j = base + i;
            s += (double)g_e2[j] * (double)g_hb[(size_t)g_perm[j]*H_ + ch];
            loc[i] = s;
        }
        tsum[tid] = s; __syncthreads();
        for (int off = 1; off < 256; off <<= 1) {
            double vv = (tid >= off) ? tsum[tid-off] : 0.0;
            __syncthreads();
            tsum[tid] += vv;
            __syncthreads();
        }
        double excl = tsum[tid] - s;
        if (tid == 0) g_P2[ch] = 0.0;
        #pragma unroll
        for (int i = 0; i < 16; ++i) g_P2[(size_t)(base+i+1)*H_ + ch] = excl + loc[i];
    }
}

__global__ void k_prefix_scalar() {
    int tid = threadIdx.x;   // 256
    __shared__ double tsum[256];
    int base = tid * 16;
    for (int pass = 0; pass < 2; ++pass) {
        const float* e = pass ? g_e2 : g_e1;
        double* P = pass ? g_D2 : g_D1;
        double loc[16]; double s = 0.0;
        #pragma unroll
        for (int i = 0; i < 16; ++i) { s += (double)e[base+i]; loc[i] = s; }
        tsum[tid] = s; __syncthreads();
        for (int off = 1; off < 256; off <<= 1) {
            double vv = (tid >= off) ? tsum[tid-off] : 0.0;
            __syncthreads();
            tsum[tid] += vv;
            __syncthreads();
        }
        double excl = tsum[tid] - s;
        if (tid == 0) P[0] = 0.0;
        #pragma unroll
        for (int i = 0; i < 16; ++i) P[base+i+1] = excl + loc[i];
        __syncthreads();
    }
}

__global__ void k_att(float* __restrict__ out,
                      const float* __restrict__ Wfc, const float* __restrict__ bfc,
                      const float* __restrict__ Wout, const float* __restrict__ bout) {
    int i   = blockIdx.x;
    int tid = threadIdx.x;   // 128
    __shared__ float h2s[H_];
    __shared__ float red[H_];
    __shared__ int   ksh;
    float s2i = g_s2[i];
    if (tid == 0) {
        float thr = -s2i;
        int lo = 0, hi = N_;
        while (lo < hi) { int mid = (lo+hi) >> 1; if (g_s1s[mid] >= thr) lo = mid+1; else hi = mid; }
        ksh = lo;
    }
    __syncthreads();
    int k = ksh;
    double f1 = exp((double)s2i + (double)g_M);
    double f2 = exp(0.01 * (double)s2i);
    double den = f1 * g_D1[k] + f2 * (g_D2[N_] - g_D2[k]);
    double num = f1 * g_P1[(size_t)k*H_ + tid]
               + f2 * (g_P2[(size_t)N_*H_ + tid] - g_P2[(size_t)k*H_ + tid]);
    h2s[tid] = (float)(num / den) + g_hb[(size_t)i*H_ + tid];
    __syncthreads();
    float acc = bfc[tid];
    #pragma unroll 8
    for (int ch = 0; ch < H_; ++ch) acc += Wfc[tid*H_ + ch] * h2s[ch];
    float h3 = acc >= 0.f ? acc : 0.01f * acc;
    red[tid] = h3 * Wout[tid];
    __syncthreads();
    for (int s = 64; s > 0; s >>= 1) {
        if (tid < s) red[tid] += red[tid + s];
        __syncthreads();
    }
    if (tid == 0) out[i] = sigmoidf_(red[0] + bout[0]);
}

extern "C" void kernel_launch(void* const* d_in, const int* in_sizes, int n_in,
                              void* d_out, int out_size) {
    const float* x     = (const float*)d_in[0];
    const float* bn1g  = (const float*)d_in[1];
    const float* bn1b  = (const float*)d_in[2];
    const float* W_ih  = (const float*)d_in[3];
    const float* W_hh  = (const float*)d_in[4];
    const float* b_ih  = (const float*)d_in[5];
    const float* b_hh  = (const float*)d_in[6];
    const float* bn2g  = (const float*)d_in[7];
    const float* bn2b  = (const float*)d_in[8];
    const float* W_t   = (const float*)d_in[9];
    const float* b_t   = (const float*)d_in[10];
    const float* a     = (const float*)d_in[11];
    const float* W_fc  = (const float*)d_in[12];
    const float* b_fc  = (const float*)d_in[13];
    const float* W_out = (const float*)d_in[14];
    const float* b_out = (const float*)d_in[15];
    float* out = (float*)d_out;

    k_init<<<(N_*H_+255)/256, 256>>>();
    k_bn1<<<dim3(D_, 16), 256>>>(x);
    k_prep<<<1, 512>>>(bn1g, bn1b, W_ih, W_hh, b_ih, b_hh, W_t, b_t, a);
    k_xg<<<dim3(NT_/64, 4), 128>>>(x);
    for (int t = 0; t < T_; ++t)
        k_gc<<<dim3(N_/64, 4), 128>>>(t);
    k_bn2s<<<N_/32, 128>>>();
    k_bn2a<<<N_, 128>>>(bn2g, bn2b);
    k_sort<<<1, 1024>>>();
    k_exp<<<(N_+255)/256, 256>>>();
    k_prefix_ch<<<H_, 256>>>();
    k_prefix_scalar<<<1, 256>>>();
    k_att<<<N_, 128>>>(out, W_fc, b_fc, W_out, b_out);
}

// round 8
// speedup vs baseline: 1.4271x; 1.0471x over previous
#include <cuda_runtime.h>
#include <cstdint>
#include <math.h>

#define N_  4096
#define D_  64
#define T_  60
#define H_  128
#define G_  512
#define NT_ 245760
#define NBLK 256          // persistent LSTM blocks
#define AP2 132           // padded A row stride (floats)

// gate dimension stored INTERLEAVED: jcol = ch*4 + gate (0=i,1=f,2=g,3=o).
// h ping-pong buffered; persistent LSTM kernel with global software barrier.

__device__ float g_xg[(size_t)T_*N_*G_];
__device__ float g_hbuf[2][N_*H_];
__device__ float g_hb[N_*H_];
__device__ float g_WpT[D_*G_];
__device__ float g_biasP[G_];
__device__ float g_Whh_i[H_*G_];
__device__ unsigned g_bar_u;
__device__ float g_bn1sum[D_], g_bn1sq[D_];
__device__ float g_bn2sum[H_], g_bn2sq[H_];
__device__ float g_wa1[H_], g_wa2[H_], g_cc[2];
__device__ float g_s1[N_], g_s2[N_];
__device__ float g_s1s[N_];
__device__ int   g_perm[N_];
__device__ float g_e1[N_], g_e2[N_];
__device__ double g_P1[(size_t)(N_+1)*H_];
__device__ double g_P2[(size_t)(N_+1)*H_];
__device__ double g_D1[N_+1], g_D2[N_+1];
__device__ float g_M;

__device__ __forceinline__ float sigmoidf_(float v) { return 1.f/(1.f + expf(-v)); }

__global__ void k_init() {
    int idx = blockIdx.x*blockDim.x + threadIdx.x;
    if (idx < N_*H_) g_hbuf[0][idx] = 0.f;
    if (idx < D_)    { g_bn1sum[idx] = 0.f; g_bn1sq[idx] = 0.f; }
    if (idx < H_)    { g_bn2sum[idx] = 0.f; g_bn2sq[idx] = 0.f; }
    if (idx == 0)    g_bar_u = 0u;
}

__global__ void k_bn1(const float* __restrict__ x) {
    int d  = blockIdx.x;
    int n0 = blockIdx.y * 256;
    float s = 0.f, q = 0.f;
    for (int idx = threadIdx.x; idx < 256*T_; idx += 256) {
        int n = n0 + idx / T_;
        int t = idx - (idx / T_) * T_;
        float v = x[(size_t)n*(D_*T_) + d*T_ + t];
        s += v; q += v*v;
    }
    __shared__ float ss[256], qq[256];
    ss[threadIdx.x] = s; qq[threadIdx.x] = q;
    __syncthreads();
    for (int st = 128; st > 0; st >>= 1) {
        if (threadIdx.x < st) { ss[threadIdx.x] += ss[threadIdx.x+st]; qq[threadIdx.x] += qq[threadIdx.x+st]; }
        __syncthreads();
    }
    if (threadIdx.x == 0) { atomicAdd(&g_bn1sum[d], ss[0]); atomicAdd(&g_bn1sq[d], qq[0]); }
}

__global__ void k_prep(const float* __restrict__ bn1g, const float* __restrict__ bn1b,
                       const float* __restrict__ W_ih, const float* __restrict__ W_hh,
                       const float* __restrict__ b_ih, const float* __restrict__ b_hh,
                       const float* __restrict__ W_t,  const float* __restrict__ b_t,
                       const float* __restrict__ a) {
    __shared__ float sc[D_], sf[D_];
    int g = threadIdx.x;  // 512 threads; g = gate*128 + ch (original layout)
    if (g < D_) {
        float inv = 1.f / (float)NT_;
        float m   = g_bn1sum[g] * inv;
        float var = g_bn1sq[g]  * inv - m*m;
        float rs  = rsqrtf(var + 1e-5f);
        sc[g] = rs * bn1g[g];
        sf[g] = bn1b[g] - m * rs * bn1g[g];
    }
    __syncthreads();
    int jcol = (g & 127) * 4 + (g >> 7);   // interleaved column
    float b = b_ih[g] + b_hh[g];
    for (int d = 0; d < D_; ++d) {
        float w = W_ih[g*D_ + d];
        b += w * sf[d];
        g_WpT[d*G_ + jcol] = w * sc[d];
    }
    g_biasP[jcol] = b;
    for (int k = 0; k < H_; ++k) g_Whh_i[k*G_ + jcol] = W_hh[g*H_ + k];
    if (g < H_) {
        float w1 = 0.f, w2 = 0.f;
        for (int h = 0; h < H_; ++h) { float wt = W_t[h*H_ + g]; w1 += wt*a[h]; w2 += wt*a[H_+h]; }
        g_wa1[g] = w1; g_wa2[g] = w2;
    }
    if (g == 0) {
        float c1 = 0.f, c2 = 0.f;
        for (int h = 0; h < H_; ++h) { c1 += b_t[h]*a[h]; c2 += b_t[h]*a[H_+h]; }
        g_cc[0] = c1; g_cc[1] = c2;
    }
}

// xg GEMM: [245760 x 64] @ [64 x 512], BN1 fused; output interleaved cols
__global__ void k_xg(const float* __restrict__ x) {
    __shared__ float a_sh[64][64];    // [k][m]
    __shared__ float b_sh[64][128];   // [k][jcol]
    int tid = threadIdx.x;
    int r0  = blockIdx.x * 64;
    int g0  = blockIdx.y * 128;
    {
        int m  = tid & 63;
        int kh = tid >> 6;
        int r  = r0 + m;
        int n  = r / T_;
        int tt = r - n*T_;
        const float* xp = x + (size_t)n*(D_*T_) + tt;
        #pragma unroll
        for (int i = 0; i < 32; ++i) {
            int k = 2*i + kh;
            a_sh[k][m] = xp[(size_t)k*T_];
        }
    }
    #pragma unroll
    for (int i = 0; i < 16; ++i) {
        int idx4 = i*128 + tid;
        int kk = idx4 >> 5, gq = idx4 & 31;
        *(float4*)&b_sh[kk][gq*4] = *(const float4*)&g_WpT[(size_t)kk*G_ + g0 + gq*4];
    }
    __syncthreads();
    int cc = tid & 15, rr = tid >> 4;
    float acc[8][8];
    #pragma unroll
    for (int i = 0; i < 8; ++i)
        #pragma unroll
        for (int j = 0; j < 8; ++j) acc[i][j] = 0.f;
    #pragma unroll 8
    for (int k = 0; k < 64; ++k) {
        float4 b0 = *(float4*)&b_sh[k][cc*8];
        float4 b1 = *(float4*)&b_sh[k][cc*8 + 4];
        #pragma unroll
        for (int i = 0; i < 8; ++i) {
            float av = a_sh[k][rr*8 + i];
            acc[i][0] += av*b0.x; acc[i][1] += av*b0.y; acc[i][2] += av*b0.z; acc[i][3] += av*b0.w;
            acc[i][4] += av*b1.x; acc[i][5] += av*b1.y; acc[i][6] += av*b1.z; acc[i][7] += av*b1.w;
        }
    }
    float4 bb0 = *(const float4*)&g_biasP[g0 + cc*8];
    float4 bb1 = *(const float4*)&g_biasP[g0 + cc*8 + 4];
    #pragma unroll
    for (int i = 0; i < 8; ++i) {
        int r  = r0 + rr*8 + i;
        int n  = r / T_;
        int tt = r - n*T_;
        float* dst = g_xg + ((size_t)tt*N_ + n)*G_ + g0 + cc*8;
        float4 o0 = make_float4(acc[i][0]+bb0.x, acc[i][1]+bb0.y, acc[i][2]+bb0.z, acc[i][3]+bb0.w);
        float4 o1 = make_float4(acc[i][4]+bb1.x, acc[i][5]+bb1.y, acc[i][6]+bb1.z, acc[i][7]+bb1.w);
        *(float4*)&dst[0] = o0;
        *(float4*)&dst[4] = o1;
    }
}

// ---------------- persistent fused LSTM (all 60 steps, 1 launch) ------------
// 256 CTAs x 128 threads. CTA covers 64 rows x 128 interleaved cols.
// W_hh slice resident in smem; c resident in registers; h ping-pong in global;
// global software barrier between steps (monotonic counter, no reset).
__global__ void __launch_bounds__(128, 2) k_lstm2() {
    extern __shared__ float sm[];
    float* Bsh = sm;               // [128][128] W_hh slice
    float* Ash = sm + 128*128;     // [64][AP2]  h tile
    const int tid = threadIdx.x;
    const int bx  = blockIdx.x;
    const int n0  = (bx & 63) * 64;
    const int j0  = (bx >> 6) * 128;
    const int cc  = tid & 15, rr = tid >> 4;

    // load W_hh slice once (128 k-rows x 128 jcols)
    #pragma unroll
    for (int i = 0; i < 32; ++i) {
        int idx4 = i*128 + tid;
        int kk = idx4 >> 5, jq = idx4 & 31;
        *(float4*)&Bsh[kk*128 + jq*4] = *(const float4*)&g_Whh_i[(size_t)kk*G_ + j0 + jq*4];
    }

    float2 cr[8];
    #pragma unroll
    for (int i = 0; i < 8; ++i) cr[i] = make_float2(0.f, 0.f);
    const int chA = (j0 >> 2) + 2*cc;

    for (int t = 0; t < T_; ++t) {
        const float* hin  = g_hbuf[t & 1];
        float*       hout = g_hbuf[(t+1) & 1];
        // load A: 64 rows x 128 ch
        #pragma unroll
        for (int i = 0; i < 16; ++i) {
            int idx4 = i*128 + tid;
            int row = idx4 >> 5, q = idx4 & 31;
            *(float4*)&Ash[row*AP2 + q*4] = *(const float4*)&hin[(size_t)(n0+row)*H_ + q*4];
        }
        __syncthreads();

        float acc[8][8];
        #pragma unroll
        for (int i = 0; i < 8; ++i)
            #pragma unroll
            for (int j = 0; j < 8; ++j) acc[i][j] = 0.f;
        const float* A = Ash + (rr*8)*AP2;
        #pragma unroll 8
        for (int k = 0; k < 128; ++k) {
            float4 b0 = *(float4*)&Bsh[k*128 + cc*8];
            float4 b1 = *(float4*)&Bsh[k*128 + cc*8 + 4];
            #pragma unroll
            for (int i = 0; i < 8; ++i) {
                float av = A[i*AP2 + k];
                acc[i][0] += av*b0.x; acc[i][1] += av*b0.y; acc[i][2] += av*b0.z; acc[i][3] += av*b0.w;
                acc[i][4] += av*b1.x; acc[i][5] += av*b1.y; acc[i][6] += av*b1.z; acc[i][7] += av*b1.w;
            }
        }

        // epilogue: add xg, cell update (c in regs), write h
        const float* xgb = g_xg + (size_t)t*N_*G_;
        #pragma unroll
        for (int i = 0; i < 8; ++i) {
            int n = n0 + rr*8 + i;
            size_t off = (size_t)n*G_ + j0 + cc*8;
            float4 x0 = *(const float4*)&xgb[off];
            float4 x1 = *(const float4*)&xgb[off + 4];
            float h0, h1;
            {
                float iv = sigmoidf_(acc[i][0] + x0.x);
                float fv = sigmoidf_(acc[i][1] + x0.y);
                float gv = tanhf    (acc[i][2] + x0.z);
                float ov = sigmoidf_(acc[i][3] + x0.w);
                float cn = fv * cr[i].x + iv * gv;
                cr[i].x = cn;
                h0 = ov * tanhf(cn);
            }
            {
                float iv = sigmoidf_(acc[i][4] + x1.x);
                float fv = sigmoidf_(acc[i][5] + x1.y);
                float gv = tanhf    (acc[i][6] + x1.z);
                float ov = sigmoidf_(acc[i][7] + x1.w);
                float cn = fv * cr[i].y + iv * gv;
                cr[i].y = cn;
                h1 = ov * tanhf(cn);
            }
            *(float2*)&hout[(size_t)n*H_ + chA] = make_float2(h0, h1);
        }

        // global barrier: monotonic counter, target NBLK*(t+1)
        __threadfence();
        __syncthreads();
        if (tid == 0) {
            atomicAdd(&g_bar_u, 1u);
            unsigned target = (unsigned)NBLK * (unsigned)(t+1);
            while (*(volatile unsigned*)&g_bar_u < target) { }
        }
        __syncthreads();
        __threadfence();
    }
}

__global__ void k_bn2s() {
    int ch = threadIdx.x;
    int n0 = blockIdx.x * 32;
    const float* hfin = g_hbuf[T_ & 1];
    float s = 0.f, q = 0.f;
    for (int r = 0; r < 32; ++r) { float v = hfin[(size_t)(n0+r)*H_ + ch]; s += v; q += v*v; }
    atomicAdd(&g_bn2sum[ch], s);
    atomicAdd(&g_bn2sq[ch],  q);
}

__global__ void k_bn2a(const float* __restrict__ g2, const float* __restrict__ b2) {
    int n = blockIdx.x, ch = threadIdx.x;
    const float* hfin = g_hbuf[T_ & 1];
    float inv = 1.f / (float)N_;
    float m   = g_bn2sum[ch] * inv;
    float var = g_bn2sq[ch]  * inv - m*m;
    float hb  = (hfin[(size_t)n*H_ + ch] - m) * rsqrtf(var + 1e-5f) * g2[ch] + b2[ch];
    g_hb[(size_t)n*H_ + ch] = hb;
    __shared__ float r1[H_], r2[H_];
    r1[ch] = hb * g_wa1[ch];
    r2[ch] = hb * g_wa2[ch];
    __syncthreads();
    for (int s = 64; s > 0; s >>= 1) {
        if (ch < s) { r1[ch] += r1[ch+s]; r2[ch] += r2[ch+s]; }
        __syncthreads();
    }
    if (ch == 0) { g_s1[n] = r1[0] + g_cc[0]; g_s2[n] = r2[0] + g_cc[1]; }
}

__global__ void k_sort() {
    __shared__ float v[N_];
    __shared__ int   p[N_];
    int tid = threadIdx.x;
    for (int i = tid; i < N_; i += 1024) { v[i] = g_s1[i]; p[i] = i; }
    __syncthreads();
    for (int kk = 2; kk <= N_; kk <<= 1) {
        for (int j = kk >> 1; j > 0; j >>= 1) {
            for (int i = tid; i < N_; i += 1024) {
                int ixj = i ^ j;
                if (ixj > i) {
                    bool up = ((i & kk) == 0);
                    bool sw = up ? (v[i] < v[ixj]) : (v[i] > v[ixj]);
                    if (sw) {
                        float tv = v[i]; v[i] = v[ixj]; v[ixj] = tv;
                        int   tp = p[i]; p[i] = p[ixj]; p[ixj] = tp;
                    }
                }
            }
            __syncthreads();
        }
    }
    for (int i = tid; i < N_; i += 1024) { g_s1s[i] = v[i]; g_perm[i] = p[i]; }
}

__global__ void k_exp() {
    int i = blockIdx.x*blockDim.x + threadIdx.x;
    float M = g_s1s[0];
    if (i == 0) g_M = M;
    if (i < N_) {
        g_e1[i] = expf(g_s1s[i] - M);
        g_e2[i] = expf(0.01f * g_s1s[i]);
    }
}

__global__ void k_prefix_ch() {
    int ch  = blockIdx.x;
    int tid = threadIdx.x;   // 256
    __shared__ double tsum[256];
    int base = tid * 16;
    {
        double loc[16]; double s = 0.0;
        #pragma unroll
        for (int i = 0; i < 16; ++i) {
            int j = base + i;
            s += (double)g_e1[j] * (double)g_hb[(size_t)g_perm[j]*H_ + ch];
            loc[i] = s;
        }
        tsum[tid] = s; __syncthreads();
        for (int off = 1; off < 256; off <<= 1) {
            double vv = (tid >= off) ? tsum[tid-off] : 0.0;
            __syncthreads();
            tsum[tid] += vv;
            __syncthreads();
        }
        double excl = tsum[tid] - s;
        if (tid == 0) g_P1[ch] = 0.0;
        #pragma unroll
        for (int i = 0; i < 16; ++i) g_P1[(size_t)(base+i+1)*H_ + ch] = excl + loc[i];
    }
    __syncthreads();
    {
        double loc[16]; double s = 0.0;
        #pragma unroll
        for (int i = 0; i < 16; ++i) {
            int j = base + i;
            s += (double)g_e2[j] * (double)g_hb[(size_t)g_perm[j]*H_ + ch];
            loc[i] = s;
        }
        tsum[tid] = s; __syncthreads();
        for (int off = 1; off < 256; off <<= 1) {
            double vv = (tid >= off) ? tsum[tid-off] : 0.0;
            __syncthreads();
            tsum[tid] += vv;
            __syncthreads();
        }
        double excl = tsum[tid] - s;
        if (tid == 0) g_P2[ch] = 0.0;
        #pragma unroll
        for (int i = 0; i < 16; ++i) g_P2[(size_t)(base+i+1)*H_ + ch] = excl + loc[i];
    }
}

__global__ void k_prefix_scalar() {
    int tid = threadIdx.x;   // 256
    __shared__ double tsum[256];
    int base = tid * 16;
    for (int pass = 0; pass < 2; ++pass) {
        const float* e = pass ? g_e2 : g_e1;
        double* P = pass ? g_D2 : g_D1;
        double loc[16]; double s = 0.0;
        #pragma unroll
        for (int i = 0; i < 16; ++i) { s += (double)e[base+i]; loc[i] = s; }
        tsum[tid] = s; __syncthreads();
        for (int off = 1; off < 256; off <<= 1) {
            double vv = (tid >= off) ? tsum[tid-off] : 0.0;
            __syncthreads();
            tsum[tid] += vv;
            __syncthreads();
        }
        double excl = tsum[tid] - s;
        if (tid == 0) P[0] = 0.0;
        #pragma unroll
        for (int i = 0; i < 16; ++i) P[base+i+1] = excl + loc[i];
        __syncthreads();
    }
}

__global__ void k_att(float* __restrict__ out,
                      const float* __restrict__ Wfc, const float* __restrict__ bfc,
                      const float* __restrict__ Wout, const float* __restrict__ bout) {
    int i   = blockIdx.x;
    int tid = threadIdx.x;   // 128
    __shared__ float h2s[H_];
    __shared__ float red[H_];
    __shared__ int   ksh;
    float s2i = g_s2[i];
    if (tid == 0) {
        float thr = -s2i;
        int lo = 0, hi = N_;
        while (lo < hi) { int mid = (lo+hi) >> 1; if (g_s1s[mid] >= thr) lo = mid+1; else hi = mid; }
        ksh = lo;
    }
    __syncthreads();
    int k = ksh;
    double f1 = exp((double)s2i + (double)g_M);
    double f2 = exp(0.01 * (double)s2i);
    double den = f1 * g_D1[k] + f2 * (g_D2[N_] - g_D2[k]);
    double num = f1 * g_P1[(size_t)k*H_ + tid]
               + f2 * (g_P2[(size_t)N_*H_ + tid] - g_P2[(size_t)k*H_ + tid]);
    h2s[tid] = (float)(num / den) + g_hb[(size_t)i*H_ + tid];
    __syncthreads();
    float acc = bfc[tid];
    #pragma unroll 8
    for (int ch = 0; ch < H_; ++ch) acc += Wfc[tid*H_ + ch] * h2s[ch];
    float h3 = acc >= 0.f ? acc : 0.01f * acc;
    red[tid] = h3 * Wout[tid];
    __syncthreads();
    for (int s = 64; s > 0; s >>= 1) {
        if (tid < s) red[tid] += red[tid + s];
        __syncthreads();
    }
    if (tid == 0) out[i] = sigmoidf_(red[0] + bout[0]);
}

extern "C" void kernel_launch(void* const* d_in, const int* in_sizes, int n_in,
                              void* d_out, int out_size) {
    const float* x     = (const float*)d_in[0];
    const float* bn1g  = (const float*)d_in[1];
    const float* bn1b  = (const float*)d_in[2];
    const float* W_ih  = (const float*)d_in[3];
    const float* W_hh  = (const float*)d_in[4];
    const float* b_ih  = (const float*)d_in[5];
    const float* b_hh  = (const float*)d_in[6];
    const float* bn2g  = (const float*)d_in[7];
    const float* bn2b  = (const float*)d_in[8];
    const float* W_t   = (const float*)d_in[9];
    const float* b_t   = (const float*)d_in[10];
    const float* a     = (const float*)d_in[11];
    const float* W_fc  = (const float*)d_in[12];
    const float* b_fc  = (const float*)d_in[13];
    const float* W_out = (const float*)d_in[14];
    const float* b_out = (const float*)d_in[15];
    float* out = (float*)d_out;

    const int lstm_smem = (128*128 + 64*AP2) * (int)sizeof(float);  // 99328 B
    cudaFuncSetAttribute(k_lstm2, cudaFuncAttributeMaxDynamicSharedMemorySize, lstm_smem);

    k_init<<<(N_*H_+255)/256, 256>>>();
    k_bn1<<<dim3(D_, 16), 256>>>(x);
    k_prep<<<1, 512>>>(bn1g, bn1b, W_ih, W_hh, b_ih, b_hh, W_t, b_t, a);
    k_xg<<<dim3(NT_/64, 4), 128>>>(x);
    k_lstm2<<<NBLK, 128, lstm_smem>>>();
    k_bn2s<<<N_/32, 128>>>();
    k_bn2a<<<N_, 128>>>(bn2g, bn2b);
    k_sort<<<1, 1024>>>();
    k_exp<<<(N_+255)/256, 256>>>();
    k_prefix_ch<<<H_, 256>>>();
    k_prefix_scalar<<<1, 256>>>();
    k_att<<<N_, 128>>>(out, W_fc, b_fc, W_out, b_out);
}